// round 6
// baseline (speedup 1.0000x reference)
#include <cuda_runtime.h>
#include <cuda_pipeline.h>
#include <math.h>

// Problem shape (fixed by setup_inputs)
#define NN 512
#define EE 64
#define OO 64
#define KK 8
#define NT 1024
#define CHN 16              // n-rows per chunk
#define NCH (NN / CHN)      // 32 chunks per iteration
#define NPAD 68             // padded priors row stride (floats)

// ---- shared memory layout (byte offsets) ----
#define OFF_STAGE   0                    // 2 x 32768 B staging ring
#define STAGE_FLTS  8192                 // floats per stage (8k*16n*64o)
#define OFF_PRIORS  65536                // [512][68] fp32 = 139264 B
#define OFF_DELTA   204800               // [8][512]  fp32 =  16384 B
#define OFF_Z       221184               // [8][64]   fp32 =   2048 B
#define OFF_V       223232               // [8][64]   fp32 =   2048 B
#define SMEM_TOTAL  225280
// aliases (stage area is idle when these are used)
#define OFF_SMAT    0                    // phase A only: [64][64] fp32 = 16 KB
#define OFF_ZRED    0                    // post-drain:  [16][8][64] fp32 = 32 KB

__global__ void __launch_bounds__(NT, 1)
routing_kernel(const float* __restrict__ emb,
               const float* __restrict__ S,
               const float* __restrict__ cc0,
               float* __restrict__ out)
{
    extern __shared__ __align__(16) char smraw[];
    float* stage = reinterpret_cast<float*>(smraw + OFF_STAGE);
    float (*priors)[NPAD] = reinterpret_cast<float(*)[NPAD]>(smraw + OFF_PRIORS);
    float (*delta)[NN]    = reinterpret_cast<float(*)[NN]>(smraw + OFF_DELTA);
    float (*zsh)[OO]      = reinterpret_cast<float(*)[OO]>(smraw + OFF_Z);
    float (*vsh)[OO]      = reinterpret_cast<float(*)[OO]>(smraw + OFF_V);
    float (*Smat)[OO]     = reinterpret_cast<float(*)[OO]>(smraw + OFF_SMAT);
    float* zred           = reinterpret_cast<float*>(smraw + OFF_ZRED);

    const int b    = blockIdx.x;
    const int t    = threadIdx.x;
    const int lane = t & 31;
    const int warp = t >> 5;
    // streaming decomposition: thread owns ALL 8 k for one (n, o) scalar
    const int oo = t & 63;          // o index
    const int nl = t >> 6;          // n within chunk [0,16)

    // ---- load S into (aliased) smem + zero delta ----
    {
        const float4* src = reinterpret_cast<const float4*>(S);
        float4* dst = reinterpret_cast<float4*>(&Smat[0][0]);
        for (int i = t; i < (EE * OO) / 4; i += NT) dst[i] = src[i];
    }
    for (int i = t; i < KK * NN; i += NT) (&delta[0][0])[i] = 0.0f;
    __syncthreads();

    // ---- Phase A: priors[n][o] = sum_e emb[b,n,e] * S[e,o] ----
    {
        const int o4A = t & 15;          // float4 of O row
        const int ngA = (t >> 4) & 31;   // n-group
        const int rep = t >> 9;          // 0/1: splits the 16 rows
        const float* embb = emb + (size_t)b * NN * EE;
        #pragma unroll 1
        for (int i = rep * 8; i < rep * 8 + 8; i++) {
            const int n = ngA + 32 * i;
            const float4* erow = reinterpret_cast<const float4*>(embb + n * EE);
            float4 acc = make_float4(0.f, 0.f, 0.f, 0.f);
            #pragma unroll
            for (int e4 = 0; e4 < EE / 4; e4++) {
                float4 a  = erow[e4];
                float4 s0 = *reinterpret_cast<const float4*>(&Smat[4*e4+0][o4A*4]);
                float4 s1 = *reinterpret_cast<const float4*>(&Smat[4*e4+1][o4A*4]);
                float4 s2 = *reinterpret_cast<const float4*>(&Smat[4*e4+2][o4A*4]);
                float4 s3 = *reinterpret_cast<const float4*>(&Smat[4*e4+3][o4A*4]);
                acc.x += a.x*s0.x + a.y*s1.x + a.z*s2.x + a.w*s3.x;
                acc.y += a.x*s0.y + a.y*s1.y + a.z*s2.y + a.w*s3.y;
                acc.z += a.x*s0.z + a.y*s1.z + a.z*s2.z + a.w*s3.z;
                acc.w += a.x*s0.w + a.y*s1.w + a.z*s2.w + a.w*s3.w;
            }
            *reinterpret_cast<float4*>(&priors[n][o4A * 4]) = acc;
        }
    }
    __syncthreads();   // Smat alias (stage area) free after this

    const float* ccb = cc0 + (size_t)b * KK * NN * OO;

    #pragma unroll 1
    for (int it = 0; it < 3; it++) {
        // ---- pipeline prologue: chunks 0 and 1 ----
        // copy mapping: 2048 float4s per chunk; idx = t + j*NT;
        // k = idx>>8, off = idx&255 (float4 within k's contiguous 4KB block)
        #pragma unroll
        for (int s = 0; s < 2; s++) {
            float* stg = stage + s * STAGE_FLTS;
            #pragma unroll
            for (int j = 0; j < 2; j++) {
                const int idx = t + j * NT;
                const int k = idx >> 8, off = idx & 255;
                __pipeline_memcpy_async(
                    stg + (size_t)idx * 4,
                    ccb + ((size_t)k * NN + s * CHN) * OO + off * 4, 16);
            }
            __pipeline_commit();
        }

        float zp[KK];
        #pragma unroll
        for (int k = 0; k < KK; k++) zp[k] = 0.f;

        #pragma unroll 1
        for (int ch = 0; ch < NCH; ch++) {
            if (ch < NCH - 1) __pipeline_wait_prior(1);
            else              __pipeline_wait_prior(0);
            __syncthreads();

            const int n = ch * CHN + nl;
            const float* stg = stage + (ch & 1) * STAGE_FLTS;

            // thread-local softmax over all 8 k
            float d[KK];
            float dm = -1e30f;
            #pragma unroll
            for (int k = 0; k < KK; k++) { d[k] = delta[k][n]; dm = fmaxf(dm, d[k]); }

            float e[KK];
            float sum = 0.f;
            #pragma unroll
            for (int k = 0; k < KK; k++) {
                const float c = stg[k * (CHN * OO) + nl * OO + oo];
                e[k] = __expf(c + (d[k] - dm));
                sum += e[k];
            }
            const float g = __fdividef(priors[n][oo], sum);
            #pragma unroll
            for (int k = 0; k < KK; k++) zp[k] += e[k] * g;

            __syncthreads();   // stage slot free for refill
            if (ch + 2 < NCH) {
                float* stg2 = stage + (ch & 1) * STAGE_FLTS;
                #pragma unroll
                for (int j = 0; j < 2; j++) {
                    const int idx = t + j * NT;
                    const int k = idx >> 8, off = idx & 255;
                    __pipeline_memcpy_async(
                        stg2 + (size_t)idx * 4,
                        ccb + ((size_t)k * NN + (ch + 2) * CHN) * OO + off * 4, 16);
                }
                __pipeline_commit();
            }
        }

        // ---- reduce z over the 16 nl-groups (zred aliases drained stage[0]) ----
        #pragma unroll
        for (int k = 0; k < KK; k++)
            zred[(nl * KK + k) * OO + oo] = zp[k];
        __syncthreads();
        if (t < KK * OO) {
            const int k = t >> 6, o = t & 63;
            float s = 0.f;
            #pragma unroll
            for (int w = 0; w < 16; w++) s += zred[(w * KK + k) * OO + o];
            zsh[k][o] = s;
        }
        __syncthreads();

        // ---- squash: warp w handles capsule k = w ----
        if (warp < KK) {
            const int k = warp;
            const float z0 = zsh[k][lane];
            const float z1 = zsh[k][lane + 32];
            float sq = z0 * z0 + z1 * z1;
            #pragma unroll
            for (int s2 = 16; s2 > 0; s2 >>= 1) sq += __shfl_xor_sync(0xffffffffu, sq, s2);
            const float f = sq / ((1.0f + sq) * sqrtf(sq + 1e-9f));
            if (it == 2) {
                float* ob = out + (size_t)b * KK * OO + (size_t)k * OO;
                ob[lane]      = f * z0;
                ob[lane + 32] = f * z1;
            } else {
                vsh[k][lane]      = f * z0;
                vsh[k][lane + 32] = f * z1;
            }
        }
        if (it == 2) break;
        __syncthreads();

        // ---- sim pass: delta[k][n] += <priors[n,:], v[k,:]> ----
        // thread t: n = t&511, k-half = t>>9 (4 k's each) -> disjoint writes
        {
            const int n  = t & 511;
            const int kh = t >> 9;
            float sim[4];
            #pragma unroll
            for (int j = 0; j < 4; j++) sim[j] = 0.f;
            #pragma unroll
            for (int o4 = 0; o4 < 16; o4++) {
                float4 pp = *reinterpret_cast<const float4*>(&priors[n][o4 * 4]);
                #pragma unroll
                for (int j = 0; j < 4; j++) {
                    float4 vv = *reinterpret_cast<const float4*>(&vsh[kh * 4 + j][o4 * 4]);
                    sim[j] += pp.x * vv.x + pp.y * vv.y + pp.z * vv.z + pp.w * vv.w;
                }
            }
            #pragma unroll
            for (int j = 0; j < 4; j++) delta[kh * 4 + j][n] += sim[j];
        }
        __syncthreads();   // delta ready; stage area free for next iter prologue
    }
}

extern "C" void kernel_launch(void* const* d_in, const int* in_sizes, int n_in,
                              void* d_out, int out_size)
{
    const float* emb = (const float*)d_in[0];   // (B, N, E) fp32
    const float* S   = (const float*)d_in[1];   // (E, O)   fp32
    const float* cc  = (const float*)d_in[2];   // (B, K, N, O) fp32
    float* out       = (float*)d_out;           // (B, K, O) fp32

    const int Bv = in_sizes[0] / (NN * EE);     // 256

    cudaFuncSetAttribute(routing_kernel,
                         cudaFuncAttributeMaxDynamicSharedMemorySize, SMEM_TOTAL);

    routing_kernel<<<Bv, NT, SMEM_TOTAL>>>(emb, S, cc, out);
}